// round 2
// baseline (speedup 1.0000x reference)
#include <cuda_runtime.h>
#include <math.h>

#define T_TOKENS 4096
#define D_DIM    1024
#define E_EXP    8
#define F_DIM    2048
#define TWO_F    4096

// ---------------- scratch (device globals; no allocs allowed) ----------------
__device__ int   g_cnt[E_EXP];
__device__ int   g_entries[E_EXP][T_TOKENS];     // packed: token*2 + slot
__device__ float g_wts[T_TOKENS][2];             // softmax routing weights
__device__ float g_h[T_TOKENS * 2][F_DIM];       // swiglu output per pair
__device__ float g_y[T_TOKENS * 2][D_DIM];       // dense2 output per pair (pre-combined)

// ---------------- kernel 0: zero counters ----------------
__global__ void zero_kernel() {
    if (threadIdx.x < E_EXP) g_cnt[threadIdx.x] = 0;
}

// ---------------- kernel 1: gate + top2 + routing ----------------
// one warp per token
__global__ void gate_kernel(const float* __restrict__ x, const float* __restrict__ gw) {
    int warp = threadIdx.x >> 5;
    int lane = threadIdx.x & 31;
    int t = blockIdx.x * 4 + warp;

    float acc[8] = {0.f,0.f,0.f,0.f,0.f,0.f,0.f,0.f};
    const float* xr = x + (size_t)t * D_DIM;
    for (int d = lane; d < D_DIM; d += 32) {
        float xv = xr[d];
        const float* g = gw + d * 8;     // gate_w is [D, 8] row-major
        #pragma unroll
        for (int e = 0; e < 8; e++) acc[e] += xv * g[e];
    }
    #pragma unroll
    for (int off = 16; off > 0; off >>= 1) {
        #pragma unroll
        for (int e = 0; e < 8; e++)
            acc[e] += __shfl_down_sync(0xffffffffu, acc[e], off);
    }
    if (lane == 0) {
        int b0 = 0; float v0 = acc[0];
        #pragma unroll
        for (int e = 1; e < 8; e++) if (acc[e] > v0) { v0 = acc[e]; b0 = e; }
        int b1 = -1; float v1 = -3.4e38f;
        #pragma unroll
        for (int e = 0; e < 8; e++) if (e != b0 && acc[e] > v1) { v1 = acc[e]; b1 = e; }
        float w0 = 1.0f / (1.0f + expf(v1 - v0));   // softmax over [v0, v1]
        g_wts[t][0] = w0;
        g_wts[t][1] = 1.0f - w0;
        int p0 = atomicAdd(&g_cnt[b0], 1);
        g_entries[b0][p0] = t * 2 + 0;
        int p1 = atomicAdd(&g_cnt[b1], 1);
        g_entries[b1][p1] = t * 2 + 1;
    }
}

// ---------------- kernel 2: grouped dense1 (x @ W1[e]^T) + bias + swiglu ----------------
// 64x64 tile, K-step 16, 256 threads, 4x4 microtile.
// grid: (TWO_F/64, maxRowTiles=64, E)
__global__ __launch_bounds__(256) void dense1_kernel(
    const float* __restrict__ x, const float* __restrict__ w1, const float* __restrict__ b1) {
    int e = blockIdx.z;
    int n = g_cnt[e];
    int rt = blockIdx.y;
    if (rt * 64 >= n) return;
    int ct = blockIdx.x;

    __shared__ float As[16][68];
    __shared__ float Bs[16][68];
    __shared__ int toks[64];

    int tid = threadIdx.x;
    if (tid < 64) {
        int r = rt * 64 + tid;
        toks[tid] = (r < n) ? g_entries[e][r] : -1;
    }
    __syncthreads();

    int arow = tid >> 2;
    int af   = tid & 3;
    int ts_a = toks[arow];
    bool a_valid = (ts_a >= 0);
    const float* xrow = x + (a_valid ? (size_t)(ts_a >> 1) * D_DIM : 0);
    const float* brow = w1 + ((size_t)e * TWO_F + (size_t)ct * 64 + arow) * D_DIM;

    int tx = tid & 15, ty = tid >> 4;
    float acc[4][4] = {};

    for (int k0 = 0; k0 < D_DIM; k0 += 16) {
        float4 av = a_valid ? *(const float4*)(xrow + k0 + af * 4)
                            : make_float4(0.f, 0.f, 0.f, 0.f);
        float4 bv = *(const float4*)(brow + k0 + af * 4);
        __syncthreads();
        As[af*4+0][arow] = av.x; As[af*4+1][arow] = av.y;
        As[af*4+2][arow] = av.z; As[af*4+3][arow] = av.w;
        Bs[af*4+0][arow] = bv.x; Bs[af*4+1][arow] = bv.y;
        Bs[af*4+2][arow] = bv.z; Bs[af*4+3][arow] = bv.w;
        __syncthreads();
        #pragma unroll
        for (int k = 0; k < 16; k++) {
            float4 a4 = *(const float4*)&As[k][ty * 4];
            float4 b4 = *(const float4*)&Bs[k][tx * 4];
            float aa[4] = {a4.x, a4.y, a4.z, a4.w};
            float bb[4] = {b4.x, b4.y, b4.z, b4.w};
            #pragma unroll
            for (int i = 0; i < 4; i++)
                #pragma unroll
                for (int j = 0; j < 4; j++)
                    acc[i][j] += aa[i] * bb[j];
        }
    }

    // epilogue: columns come in (gate, value) adjacent pairs; tx*4 is even-aligned
    #pragma unroll
    for (int i = 0; i < 4; i++) {
        int r = ty * 4 + i;
        int ts = toks[r];
        if (ts < 0) continue;
        float hv[2];
        #pragma unroll
        for (int p = 0; p < 2; p++) {
            int c = ct * 64 + tx * 4 + p * 2;            // even col = gate
            float gpre = acc[i][p*2]   + b1[e * TWO_F + c];
            float vpre = acc[i][p*2+1] + b1[e * TWO_F + c + 1];
            float gg = fminf(gpre, 9.0f);
            float vv = fminf(fmaxf(vpre, -9.0f), 9.0f);
            hv[p] = gg * (1.0f / (1.0f + expf(-1.702f * gg))) * (vv + 1.0f);
        }
        int f = ct * 32 + tx * 2;                        // = c/2
        *(float2*)&g_h[ts][f] = make_float2(hv[0], hv[1]);
    }
}

// ---------------- kernel 3: grouped dense2 (h @ W2[e]^T) + bias + routing scale ----------------
// grid: (D_DIM/64, maxRowTiles=64, E)
__global__ __launch_bounds__(256) void dense2_kernel(
    const float* __restrict__ w2, const float* __restrict__ b2) {
    int e = blockIdx.z;
    int n = g_cnt[e];
    int rt = blockIdx.y;
    if (rt * 64 >= n) return;
    int ct = blockIdx.x;

    __shared__ float As[16][68];
    __shared__ float Bs[16][68];
    __shared__ int toks[64];

    int tid = threadIdx.x;
    if (tid < 64) {
        int r = rt * 64 + tid;
        toks[tid] = (r < n) ? g_entries[e][r] : -1;
    }
    __syncthreads();

    int arow = tid >> 2;
    int af   = tid & 3;
    int ts_a = toks[arow];
    bool a_valid = (ts_a >= 0);
    const float* hrow = g_h[a_valid ? ts_a : 0];
    const float* brow = w2 + ((size_t)e * D_DIM + (size_t)ct * 64 + arow) * F_DIM;

    int tx = tid & 15, ty = tid >> 4;
    float acc[4][4] = {};

    for (int k0 = 0; k0 < F_DIM; k0 += 16) {
        float4 av = a_valid ? *(const float4*)(hrow + k0 + af * 4)
                            : make_float4(0.f, 0.f, 0.f, 0.f);
        float4 bv = *(const float4*)(brow + k0 + af * 4);
        __syncthreads();
        As[af*4+0][arow] = av.x; As[af*4+1][arow] = av.y;
        As[af*4+2][arow] = av.z; As[af*4+3][arow] = av.w;
        Bs[af*4+0][arow] = bv.x; Bs[af*4+1][arow] = bv.y;
        Bs[af*4+2][arow] = bv.z; Bs[af*4+3][arow] = bv.w;
        __syncthreads();
        #pragma unroll
        for (int k = 0; k < 16; k++) {
            float4 a4 = *(const float4*)&As[k][ty * 4];
            float4 b4 = *(const float4*)&Bs[k][tx * 4];
            float aa[4] = {a4.x, a4.y, a4.z, a4.w};
            float bb[4] = {b4.x, b4.y, b4.z, b4.w};
            #pragma unroll
            for (int i = 0; i < 4; i++)
                #pragma unroll
                for (int j = 0; j < 4; j++)
                    acc[i][j] += aa[i] * bb[j];
        }
    }

    #pragma unroll
    for (int i = 0; i < 4; i++) {
        int r = ty * 4 + i;
        int ts = toks[r];
        if (ts < 0) continue;
        float w = g_wts[ts >> 1][ts & 1];
        #pragma unroll
        for (int j = 0; j < 4; j++) {
            int d = ct * 64 + tx * 4 + j;
            g_y[ts][d] = (acc[i][j] + b2[e * D_DIM + d]) * w;
        }
    }
}

// ---------------- kernel 4: combine two expert contributions per token ----------------
__global__ void combine_kernel(float* __restrict__ out) {
    int i = blockIdx.x * blockDim.x + threadIdx.x;   // over 4096*256 float4s
    int t = i >> 8, q = i & 255;
    float4 a = ((const float4*)g_y[t * 2 + 0])[q];
    float4 b = ((const float4*)g_y[t * 2 + 1])[q];
    ((float4*)out)[i] = make_float4(a.x + b.x, a.y + b.y, a.z + b.z, a.w + b.w);
}

// ---------------- launch ----------------
extern "C" void kernel_launch(void* const* d_in, const int* in_sizes, int n_in,
                              void* d_out, int out_size) {
    const float* x  = (const float*)d_in[0];
    const float* gw = (const float*)d_in[1];
    const float* w1 = (const float*)d_in[2];
    const float* b1 = (const float*)d_in[3];
    const float* w2 = (const float*)d_in[4];
    const float* b2 = (const float*)d_in[5];
    float* out = (float*)d_out;

    zero_kernel<<<1, 32>>>();
    gate_kernel<<<T_TOKENS / 4, 128>>>(x, gw);
    dense1_kernel<<<dim3(TWO_F / 64, T_TOKENS / 64, E_EXP), 256>>>(x, w1, b1);
    dense2_kernel<<<dim3(D_DIM / 64, T_TOKENS / 64, E_EXP), 256>>>(w2, b2);
    combine_kernel<<<(T_TOKENS * D_DIM / 4) / 256, 256>>>(out);
}

// round 5
// speedup vs baseline: 2.5852x; 2.5852x over previous
#include <cuda_runtime.h>
#include <cuda_bf16.h>
#include <math.h>
#include <stdint.h>

#define T_TOKENS 4096
#define D_DIM    1024
#define E_EXP    8
#define F_DIM    2048
#define TWO_F    4096
#define NPAIR    (T_TOKENS * 2)

#define TM 128
#define TN 128
#define KB 64                     // K elements per stage (64 bf16 = 128B rows, SW128)
#define TILE_BYTES 16384          // 128 rows * 128 B
#define STAGE_BYTES (4 * TILE_BYTES)
#define NSTAGE 3
#define SMEM_BYTES (1024 + NSTAGE * STAGE_BYTES)

// ---------------- scratch (device globals; no allocs allowed) ----------------
__device__ int   g_cnt[E_EXP];
__device__ int   g_entries[E_EXP][T_TOKENS];
__device__ float g_wts[T_TOKENS][2];
__device__ __nv_bfloat16 g_xh[T_TOKENS * D_DIM];
__device__ __nv_bfloat16 g_xl[T_TOKENS * D_DIM];
__device__ __nv_bfloat16 g_w1h[(size_t)E_EXP * TWO_F * D_DIM];
__device__ __nv_bfloat16 g_w1l[(size_t)E_EXP * TWO_F * D_DIM];
__device__ __nv_bfloat16 g_w2h[(size_t)E_EXP * D_DIM * F_DIM];
__device__ __nv_bfloat16 g_w2l[(size_t)E_EXP * D_DIM * F_DIM];
__device__ __nv_bfloat16 g_hh[(size_t)NPAIR * F_DIM];
__device__ __nv_bfloat16 g_hl[(size_t)NPAIR * F_DIM];
__device__ float g_y[(size_t)NPAIR * D_DIM];

// ---------------- helpers ----------------
__device__ __forceinline__ uint32_t smem_u32(const void* p) {
    uint32_t a;
    asm("{ .reg .u64 t; cvta.to.shared.u64 t, %1; cvt.u32.u64 %0, t; }" : "=r"(a) : "l"(p));
    return a;
}
__device__ __forceinline__ uint32_t sw128(uint32_t o) { return o ^ ((o >> 3) & 0x70); }

__device__ __forceinline__ void cp16(uint32_t dst, const void* src) {
    asm volatile("cp.async.cg.shared.global [%0], [%1], 16;" :: "r"(dst), "l"(src));
}
#define CP_COMMIT() asm volatile("cp.async.commit_group;" ::: "memory")
#define CP_WAIT(n)  asm volatile("cp.async.wait_group %0;" :: "n"(n) : "memory")

__device__ __forceinline__ void ldsm4(uint32_t* r, uint32_t addr) {
    asm volatile("ldmatrix.sync.aligned.m8n8.x4.shared.b16 {%0,%1,%2,%3}, [%4];"
        : "=r"(r[0]), "=r"(r[1]), "=r"(r[2]), "=r"(r[3]) : "r"(addr));
}
__device__ __forceinline__ void mma16816(float* d, const uint32_t* a, uint32_t b0, uint32_t b1) {
    asm volatile("mma.sync.aligned.m16n8k16.row.col.f32.bf16.bf16.f32 "
        "{%0,%1,%2,%3}, {%4,%5,%6,%7}, {%8,%9}, {%0,%1,%2,%3};"
        : "+f"(d[0]), "+f"(d[1]), "+f"(d[2]), "+f"(d[3])
        : "r"(a[0]), "r"(a[1]), "r"(a[2]), "r"(a[3]), "r"(b0), "r"(b1));
}

// ---------------- kernel 0: zero counters ----------------
__global__ void zero_kernel() { if (threadIdx.x < E_EXP) g_cnt[threadIdx.x] = 0; }

// ---------------- conversion: fp32 -> bf16 hi + lo ----------------
__device__ __forceinline__ void cvt4(float4 f, uint2& H, uint2& L) {
    __nv_bfloat16 h0 = __float2bfloat16(f.x), h1 = __float2bfloat16(f.y);
    __nv_bfloat16 h2 = __float2bfloat16(f.z), h3 = __float2bfloat16(f.w);
    __nv_bfloat16 l0 = __float2bfloat16(f.x - __bfloat162float(h0));
    __nv_bfloat16 l1 = __float2bfloat16(f.y - __bfloat162float(h1));
    __nv_bfloat16 l2 = __float2bfloat16(f.z - __bfloat162float(h2));
    __nv_bfloat16 l3 = __float2bfloat16(f.w - __bfloat162float(h3));
    H.x = (uint32_t)__bfloat16_as_ushort(h0) | ((uint32_t)__bfloat16_as_ushort(h1) << 16);
    H.y = (uint32_t)__bfloat16_as_ushort(h2) | ((uint32_t)__bfloat16_as_ushort(h3) << 16);
    L.x = (uint32_t)__bfloat16_as_ushort(l0) | ((uint32_t)__bfloat16_as_ushort(l1) << 16);
    L.y = (uint32_t)__bfloat16_as_ushort(l2) | ((uint32_t)__bfloat16_as_ushort(l3) << 16);
}
__global__ void cvt_x_kernel(const float4* __restrict__ src) {
    int i = blockIdx.x * blockDim.x + threadIdx.x;
    if (i >= T_TOKENS * D_DIM / 4) return;
    uint2 H, L; cvt4(src[i], H, L);
    ((uint2*)g_xh)[i] = H; ((uint2*)g_xl)[i] = L;
}
__global__ void cvt_w1_kernel(const float4* __restrict__ src) {
    int i = blockIdx.x * blockDim.x + threadIdx.x;
    if (i >= E_EXP * TWO_F * D_DIM / 4) return;
    uint2 H, L; cvt4(src[i], H, L);
    ((uint2*)g_w1h)[i] = H; ((uint2*)g_w1l)[i] = L;
}
__global__ void cvt_w2_kernel(const float4* __restrict__ src) {
    int i = blockIdx.x * blockDim.x + threadIdx.x;
    if (i >= E_EXP * D_DIM * F_DIM / 4) return;
    uint2 H, L; cvt4(src[i], H, L);
    ((uint2*)g_w2h)[i] = H; ((uint2*)g_w2l)[i] = L;
}

// ---------------- kernel 1: gate + top2 + routing ----------------
__global__ void gate_kernel(const float* __restrict__ x, const float* __restrict__ gw) {
    int warp = threadIdx.x >> 5;
    int lane = threadIdx.x & 31;
    int t = blockIdx.x * 4 + warp;
    float acc[8] = {0.f,0.f,0.f,0.f,0.f,0.f,0.f,0.f};
    const float* xr = x + (size_t)t * D_DIM;
    for (int d = lane; d < D_DIM; d += 32) {
        float xv = xr[d];
        const float* g = gw + d * 8;
        #pragma unroll
        for (int e = 0; e < 8; e++) acc[e] += xv * g[e];
    }
    #pragma unroll
    for (int off = 16; off > 0; off >>= 1)
        #pragma unroll
        for (int e = 0; e < 8; e++)
            acc[e] += __shfl_down_sync(0xffffffffu, acc[e], off);
    if (lane == 0) {
        int b0 = 0; float v0 = acc[0];
        #pragma unroll
        for (int e = 1; e < 8; e++) if (acc[e] > v0) { v0 = acc[e]; b0 = e; }
        int b1 = -1; float v1 = -3.4e38f;
        #pragma unroll
        for (int e = 0; e < 8; e++) if (e != b0 && acc[e] > v1) { v1 = acc[e]; b1 = e; }
        float w0 = 1.0f / (1.0f + expf(v1 - v0));
        g_wts[t][0] = w0;
        g_wts[t][1] = 1.0f - w0;
        int p0 = atomicAdd(&g_cnt[b0], 1);
        g_entries[b0][p0] = t * 2 + 0;
        int p1 = atomicAdd(&g_cnt[b1], 1);
        g_entries[b1][p1] = t * 2 + 1;
    }
}

// ---------------- shared GEMM machinery ----------------
// smem: [0..512) s_tok, [512..1024) s_val, tiles at 1024: stage{0..2} x {AH,AL,BH,BL}
__device__ __forceinline__ void stage_load(
    uint32_t sb, int buf, int k0, int tid,
    const int* s_tok, bool a_is_pair,   // a_is_pair: token = ts>>1 (dense1) else ts (dense2)
    const __nv_bfloat16* Ah, const __nv_bfloat16* Al, int lda,
    const __nv_bfloat16* Bh, const __nv_bfloat16* Bl, size_t brow0, int ldb)
{
    uint32_t base = sb + 1024 + buf * STAGE_BYTES;
    #pragma unroll
    for (int ii = 0; ii < 4; ii++) {
        int i = tid + ii * 256;
        int r = i >> 3, v = i & 7;
        uint32_t dsw = sw128((uint32_t)(r * 128 + v * 16));
        int ts = s_tok[r];
        size_t ar = (size_t)(a_is_pair ? (ts >> 1) : ts) * lda + k0 + v * 8;
        size_t wr = (brow0 + r) * (size_t)ldb + k0 + v * 8;
        cp16(base + 0 * TILE_BYTES + dsw, Ah + ar);
        cp16(base + 1 * TILE_BYTES + dsw, Al + ar);
        cp16(base + 2 * TILE_BYTES + dsw, Bh + wr);
        cp16(base + 3 * TILE_BYTES + dsw, Bl + wr);
    }
    CP_COMMIT();
}

__device__ __forceinline__ void stage_compute(
    uint32_t sb, int buf, int wm, int wn, int lane, float acc[2][8][4])
{
    uint32_t base = sb + 1024 + buf * STAGE_BYTES;
    int lrow = lane & 15, lk = (lane >> 4) * 16;
    #pragma unroll
    for (int ks = 0; ks < 4; ks++) {
        int kb = ks * 32;
        uint32_t ah[2][4], al[2][4], bh[4][4], bl[4][4];
        #pragma unroll
        for (int mt = 0; mt < 2; mt++) {
            uint32_t ro = (uint32_t)((wm * 32 + mt * 16 + lrow) * 128 + kb + lk);
            ldsm4(ah[mt], base + 0 * TILE_BYTES + sw128(ro));
            ldsm4(al[mt], base + 1 * TILE_BYTES + sw128(ro));
        }
        #pragma unroll
        for (int p = 0; p < 4; p++) {
            uint32_t ro = (uint32_t)((wn * 64 + p * 16 + lrow) * 128 + kb + lk);
            ldsm4(bh[p], base + 2 * TILE_BYTES + sw128(ro));
            ldsm4(bl[p], base + 3 * TILE_BYTES + sw128(ro));
        }
        #pragma unroll
        for (int mt = 0; mt < 2; mt++)
            #pragma unroll
            for (int p = 0; p < 4; p++) {
                mma16816(acc[mt][2*p],   ah[mt], bh[p][0], bh[p][2]);
                mma16816(acc[mt][2*p],   ah[mt], bl[p][0], bl[p][2]);
                mma16816(acc[mt][2*p],   al[mt], bh[p][0], bh[p][2]);
                mma16816(acc[mt][2*p+1], ah[mt], bh[p][1], bh[p][3]);
                mma16816(acc[mt][2*p+1], ah[mt], bl[p][1], bl[p][3]);
                mma16816(acc[mt][2*p+1], al[mt], bh[p][1], bh[p][3]);
            }
    }
}

// ---------------- kernel 2: dense1 (HMMA split-bf16) + swiglu -> h hi/lo ----------------
__global__ __launch_bounds__(256, 1) void dense1_mma(const float* __restrict__ b1) {
    int e = blockIdx.z, rt = blockIdx.y, ct = blockIdx.x;
    int n = g_cnt[e];
    if (rt * TM >= n) return;

    extern __shared__ char smem[];
    int* s_tok = (int*)smem;
    int* s_val = (int*)(smem + 512);
    uint32_t sb = smem_u32(smem);
    int tid = threadIdx.x, lane = tid & 31, wid = tid >> 5;
    int wm = wid >> 1, wn = wid & 1;

    if (tid < TM) {
        int rg = rt * TM + tid;
        int cl = rg < n ? rg : n - 1;
        s_tok[tid] = g_entries[e][cl];
        s_val[tid] = rg < n;
    }
    __syncthreads();

    float acc[2][8][4];
    #pragma unroll
    for (int a = 0; a < 2; a++)
        #pragma unroll
        for (int b = 0; b < 8; b++)
            #pragma unroll
            for (int c = 0; c < 4; c++) acc[a][b][c] = 0.f;

    size_t brow0 = (size_t)e * TWO_F + (size_t)ct * TN;
    const int NS = D_DIM / KB;  // 16
    stage_load(sb, 0, 0, tid, s_tok, true, g_xh, g_xl, D_DIM, g_w1h, g_w1l, brow0, D_DIM);
    stage_load(sb, 1, KB, tid, s_tok, true, g_xh, g_xl, D_DIM, g_w1h, g_w1l, brow0, D_DIM);
    for (int s = 0; s < NS; s++) {
        if (s + 1 < NS) { CP_WAIT(1); } else { CP_WAIT(0); }
        __syncthreads();
        if (s + 2 < NS)
            stage_load(sb, (s + 2) % NSTAGE, (s + 2) * KB, tid, s_tok, true,
                       g_xh, g_xl, D_DIM, g_w1h, g_w1l, brow0, D_DIM);
        stage_compute(sb, s % NSTAGE, wm, wn, lane, acc);
    }

    // epilogue: swiglu on (gate, value) pairs — adjacent even/odd cols
    #pragma unroll
    for (int mt = 0; mt < 2; mt++) {
        #pragma unroll
        for (int nt = 0; nt < 8; nt++) {
            int c = ct * TN + wn * 64 + nt * 8 + (lane & 3) * 2;
            float bg = b1[e * TWO_F + c];
            float bv = b1[e * TWO_F + c + 1];
            #pragma unroll
            for (int hrow = 0; hrow < 2; hrow++) {
                int r = wm * 32 + mt * 16 + (lane >> 2) + hrow * 8;
                if (!s_val[r]) continue;
                int ts = s_tok[r];
                float gpre = acc[mt][nt][hrow * 2 + 0] + bg;
                float vpre = acc[mt][nt][hrow * 2 + 1] + bv;
                float gg = fminf(gpre, 9.0f);
                float vv = fminf(fmaxf(vpre, -9.0f), 9.0f);
                float h = gg * (1.0f / (1.0f + expf(-1.702f * gg))) * (vv + 1.0f);
                __nv_bfloat16 hh = __float2bfloat16(h);
                __nv_bfloat16 hl = __float2bfloat16(h - __bfloat162float(hh));
                size_t f = (size_t)ts * F_DIM + (c >> 1);
                g_hh[f] = hh;
                g_hl[f] = hl;
            }
        }
    }
}

// ---------------- kernel 3: dense2 (HMMA split-bf16) + bias + routing scale ----------------
__global__ __launch_bounds__(256, 1) void dense2_mma(const float* __restrict__ b2) {
    int e = blockIdx.z, rt = blockIdx.y, ct = blockIdx.x;
    int n = g_cnt[e];
    if (rt * TM >= n) return;

    extern __shared__ char smem[];
    int* s_tok = (int*)smem;
    int* s_val = (int*)(smem + 512);
    uint32_t sb = smem_u32(smem);
    int tid = threadIdx.x, lane = tid & 31, wid = tid >> 5;
    int wm = wid >> 1, wn = wid & 1;

    if (tid < TM) {
        int rg = rt * TM + tid;
        int cl = rg < n ? rg : n - 1;
        s_tok[tid] = g_entries[e][cl];
        s_val[tid] = rg < n;
    }
    __syncthreads();

    float acc[2][8][4];
    #pragma unroll
    for (int a = 0; a < 2; a++)
        #pragma unroll
        for (int b = 0; b < 8; b++)
            #pragma unroll
            for (int c = 0; c < 4; c++) acc[a][b][c] = 0.f;

    size_t brow0 = (size_t)e * D_DIM + (size_t)ct * TN;
    const int NS = F_DIM / KB;  // 32
    stage_load(sb, 0, 0, tid, s_tok, false, g_hh, g_hl, F_DIM, g_w2h, g_w2l, brow0, F_DIM);
    stage_load(sb, 1, KB, tid, s_tok, false, g_hh, g_hl, F_DIM, g_w2h, g_w2l, brow0, F_DIM);
    for (int s = 0; s < NS; s++) {
        if (s + 1 < NS) { CP_WAIT(1); } else { CP_WAIT(0); }
        __syncthreads();
        if (s + 2 < NS)
            stage_load(sb, (s + 2) % NSTAGE, (s + 2) * KB, tid, s_tok, false,
                       g_hh, g_hl, F_DIM, g_w2h, g_w2l, brow0, F_DIM);
        stage_compute(sb, s % NSTAGE, wm, wn, lane, acc);
    }

    #pragma unroll
    for (int mt = 0; mt < 2; mt++) {
        #pragma unroll
        for (int hrow = 0; hrow < 2; hrow++) {
            int r = wm * 32 + mt * 16 + (lane >> 2) + hrow * 8;
            if (!s_val[r]) continue;
            int ts = s_tok[r];
            float wgt = g_wts[ts >> 1][ts & 1];
            float* yrow = g_y + (size_t)ts * D_DIM;
            #pragma unroll
            for (int nt = 0; nt < 8; nt++) {
                int c = ct * TN + wn * 64 + nt * 8 + (lane & 3) * 2;
                float y0 = (acc[mt][nt][hrow * 2 + 0] + b2[e * D_DIM + c]) * wgt;
                float y1 = (acc[mt][nt][hrow * 2 + 1] + b2[e * D_DIM + c + 1]) * wgt;
                yrow[c] = y0;
                yrow[c + 1] = y1;
            }
        }
    }
}

// ---------------- kernel 4: combine ----------------
__global__ void combine_kernel(float* __restrict__ out) {
    int i = blockIdx.x * blockDim.x + threadIdx.x;
    int t = i >> 8, q = i & 255;
    float4 a = ((const float4*)(g_y + (size_t)(t * 2 + 0) * D_DIM))[q];
    float4 b = ((const float4*)(g_y + (size_t)(t * 2 + 1) * D_DIM))[q];
    ((float4*)out)[i] = make_float4(a.x + b.x, a.y + b.y, a.z + b.z, a.w + b.w);
}

// ---------------- launch ----------------
extern "C" void kernel_launch(void* const* d_in, const int* in_sizes, int n_in,
                              void* d_out, int out_size) {
    const float* x  = (const float*)d_in[0];
    const float* gw = (const float*)d_in[1];
    const float* w1 = (const float*)d_in[2];
    const float* b1 = (const float*)d_in[3];
    const float* w2 = (const float*)d_in[4];
    const float* b2 = (const float*)d_in[5];
    float* out = (float*)d_out;

    cudaFuncSetAttribute(dense1_mma, cudaFuncAttributeMaxDynamicSharedMemorySize, SMEM_BYTES);
    cudaFuncSetAttribute(dense2_mma, cudaFuncAttributeMaxDynamicSharedMemorySize, SMEM_BYTES);

    zero_kernel<<<1, 32>>>();
    cvt_x_kernel<<<(T_TOKENS * D_DIM / 4 + 255) / 256, 256>>>((const float4*)x);
    cvt_w1_kernel<<<(E_EXP * TWO_F * D_DIM / 4 + 255) / 256, 256>>>((const float4*)w1);
    cvt_w2_kernel<<<(E_EXP * D_DIM * F_DIM / 4 + 255) / 256, 256>>>((const float4*)w2);
    gate_kernel<<<T_TOKENS / 4, 128>>>(x, gw);
    dense1_mma<<<dim3(TWO_F / TN, T_TOKENS / TM, E_EXP), 256, SMEM_BYTES>>>(b1);
    dense2_mma<<<dim3(D_DIM / TN, T_TOKENS / TM, E_EXP), 256, SMEM_BYTES>>>(b2);
    combine_kernel<<<(T_TOKENS * D_DIM / 4) / 256, 256>>>(out);
}

// round 7
// speedup vs baseline: 2.6516x; 1.0257x over previous
#include <cuda_runtime.h>
#include <cuda_bf16.h>
#include <math.h>
#include <stdint.h>

#define T_TOKENS 4096
#define D_DIM    1024
#define E_EXP    8
#define F_DIM    2048
#define TWO_F    4096
#define NPAIR    (T_TOKENS * 2)

#define TM 128
#define TN 128
#define KB 64                     // K elements per stage (64 bf16 = 128B rows, SW128)
#define TILE_BYTES 16384          // 128 rows * 128 B
#define STAGE_BYTES (4 * TILE_BYTES)
#define NSTAGE 3
#define SMEM_BYTES (1024 + NSTAGE * STAGE_BYTES)

// ---------------- scratch (device globals; no allocs allowed) ----------------
__device__ int   g_cnt[E_EXP];
__device__ int   g_entries[E_EXP][T_TOKENS];
__device__ float g_wts[T_TOKENS][2];
__device__ __nv_bfloat16 g_xh[T_TOKENS * D_DIM];
__device__ __nv_bfloat16 g_xl[T_TOKENS * D_DIM];
__device__ __nv_bfloat16 g_w1h[(size_t)E_EXP * TWO_F * D_DIM];
__device__ __nv_bfloat16 g_w1l[(size_t)E_EXP * TWO_F * D_DIM];
__device__ __nv_bfloat16 g_w2h[(size_t)E_EXP * D_DIM * F_DIM];
__device__ __nv_bfloat16 g_w2l[(size_t)E_EXP * D_DIM * F_DIM];
__device__ __nv_bfloat16 g_hh[(size_t)NPAIR * F_DIM];
__device__ __nv_bfloat16 g_hl[(size_t)NPAIR * F_DIM];

// ---------------- helpers ----------------
__device__ __forceinline__ uint32_t smem_u32(const void* p) {
    uint32_t a;
    asm("{ .reg .u64 t; cvta.to.shared.u64 t, %1; cvt.u32.u64 %0, t; }" : "=r"(a) : "l"(p));
    return a;
}
__device__ __forceinline__ uint32_t sw128(uint32_t o) { return o ^ ((o >> 3) & 0x70); }

__device__ __forceinline__ void cp16(uint32_t dst, const void* src) {
    asm volatile("cp.async.cg.shared.global [%0], [%1], 16;" :: "r"(dst), "l"(src));
}
#define CP_COMMIT() asm volatile("cp.async.commit_group;" ::: "memory")
#define CP_WAIT(n)  asm volatile("cp.async.wait_group %0;" :: "n"(n) : "memory")

__device__ __forceinline__ void ldsm4(uint32_t* r, uint32_t addr) {
    asm volatile("ldmatrix.sync.aligned.m8n8.x4.shared.b16 {%0,%1,%2,%3}, [%4];"
        : "=r"(r[0]), "=r"(r[1]), "=r"(r[2]), "=r"(r[3]) : "r"(addr));
}
__device__ __forceinline__ void mma16816(float* d, const uint32_t* a, uint32_t b0, uint32_t b1) {
    asm volatile("mma.sync.aligned.m16n8k16.row.col.f32.bf16.bf16.f32 "
        "{%0,%1,%2,%3}, {%4,%5,%6,%7}, {%8,%9}, {%0,%1,%2,%3};"
        : "+f"(d[0]), "+f"(d[1]), "+f"(d[2]), "+f"(d[3])
        : "r"(a[0]), "r"(a[1]), "r"(a[2]), "r"(a[3]), "r"(b0), "r"(b1));
}

// ---------------- kernel 0: zero output + counters ----------------
__global__ void zero_all_kernel(float4* __restrict__ out) {
    int i = blockIdx.x * blockDim.x + threadIdx.x;
    if (i < T_TOKENS * D_DIM / 4) out[i] = make_float4(0.f, 0.f, 0.f, 0.f);
    if (blockIdx.x == 0 && threadIdx.x < E_EXP) g_cnt[threadIdx.x] = 0;
}

// ---------------- conversion: fp32 -> bf16 hi + lo (all three tensors, one launch) ----------------
__device__ __forceinline__ void cvt4(float4 f, uint2& H, uint2& L) {
    __nv_bfloat16 h0 = __float2bfloat16(f.x), h1 = __float2bfloat16(f.y);
    __nv_bfloat16 h2 = __float2bfloat16(f.z), h3 = __float2bfloat16(f.w);
    __nv_bfloat16 l0 = __float2bfloat16(f.x - __bfloat162float(h0));
    __nv_bfloat16 l1 = __float2bfloat16(f.y - __bfloat162float(h1));
    __nv_bfloat16 l2 = __float2bfloat16(f.z - __bfloat162float(h2));
    __nv_bfloat16 l3 = __float2bfloat16(f.w - __bfloat162float(h3));
    H.x = (uint32_t)__bfloat16_as_ushort(h0) | ((uint32_t)__bfloat16_as_ushort(h1) << 16);
    H.y = (uint32_t)__bfloat16_as_ushort(h2) | ((uint32_t)__bfloat16_as_ushort(h3) << 16);
    L.x = (uint32_t)__bfloat16_as_ushort(l0) | ((uint32_t)__bfloat16_as_ushort(l1) << 16);
    L.y = (uint32_t)__bfloat16_as_ushort(l2) | ((uint32_t)__bfloat16_as_ushort(l3) << 16);
}
#define NX4  (T_TOKENS * D_DIM / 4)
#define NW14 (E_EXP * TWO_F * D_DIM / 4)
#define NW24 (E_EXP * D_DIM * F_DIM / 4)
__global__ void cvt_all_kernel(const float4* __restrict__ x,
                               const float4* __restrict__ w1,
                               const float4* __restrict__ w2) {
    int i = blockIdx.x * blockDim.x + threadIdx.x;
    if (i < NW14) {
        uint2 H, L; cvt4(w1[i], H, L);
        ((uint2*)g_w1h)[i] = H; ((uint2*)g_w1l)[i] = L;
    } else if (i < NW14 + NW24) {
        int j = i - NW14;
        uint2 H, L; cvt4(w2[j], H, L);
        ((uint2*)g_w2h)[j] = H; ((uint2*)g_w2l)[j] = L;
    } else if (i < NW14 + NW24 + NX4) {
        int j = i - NW14 - NW24;
        uint2 H, L; cvt4(x[j], H, L);
        ((uint2*)g_xh)[j] = H; ((uint2*)g_xl)[j] = L;
    }
}

// ---------------- kernel 1: gate + top2 + routing ----------------
__global__ void gate_kernel(const float* __restrict__ x, const float* __restrict__ gw) {
    int warp = threadIdx.x >> 5;
    int lane = threadIdx.x & 31;
    int t = blockIdx.x * 4 + warp;
    float acc[8] = {0.f,0.f,0.f,0.f,0.f,0.f,0.f,0.f};
    const float* xr = x + (size_t)t * D_DIM;
    for (int d = lane; d < D_DIM; d += 32) {
        float xv = xr[d];
        const float* g = gw + d * 8;
        #pragma unroll
        for (int e = 0; e < 8; e++) acc[e] += xv * g[e];
    }
    #pragma unroll
    for (int off = 16; off > 0; off >>= 1)
        #pragma unroll
        for (int e = 0; e < 8; e++)
            acc[e] += __shfl_down_sync(0xffffffffu, acc[e], off);
    if (lane == 0) {
        int b0 = 0; float v0 = acc[0];
        #pragma unroll
        for (int e = 1; e < 8; e++) if (acc[e] > v0) { v0 = acc[e]; b0 = e; }
        int b1 = -1; float v1 = -3.4e38f;
        #pragma unroll
        for (int e = 0; e < 8; e++) if (e != b0 && acc[e] > v1) { v1 = acc[e]; b1 = e; }
        float w0 = 1.0f / (1.0f + expf(v1 - v0));
        g_wts[t][0] = w0;
        g_wts[t][1] = 1.0f - w0;
        int p0 = atomicAdd(&g_cnt[b0], 1);
        g_entries[b0][p0] = t * 2 + 0;
        int p1 = atomicAdd(&g_cnt[b1], 1);
        g_entries[b1][p1] = t * 2 + 1;
    }
}

// ---------------- shared GEMM machinery ----------------
// smem: [0..512) s_tok, [512..1024) s_val, tiles at 1024: stage{0..2} x {AH,AL,BH,BL}
__device__ __forceinline__ void stage_load(
    uint32_t sb, int buf, int k0, int tid,
    const int* s_tok, bool a_is_pair,
    const __nv_bfloat16* Ah, const __nv_bfloat16* Al, int lda,
    const __nv_bfloat16* Bh, const __nv_bfloat16* Bl, size_t brow0, int ldb)
{
    uint32_t base = sb + 1024 + buf * STAGE_BYTES;
    #pragma unroll
    for (int ii = 0; ii < 4; ii++) {
        int i = tid + ii * 256;
        int r = i >> 3, v = i & 7;
        uint32_t dsw = sw128((uint32_t)(r * 128 + v * 16));
        int ts = s_tok[r];
        size_t ar = (size_t)(a_is_pair ? (ts >> 1) : ts) * lda + k0 + v * 8;
        size_t wr = (brow0 + r) * (size_t)ldb + k0 + v * 8;
        cp16(base + 0 * TILE_BYTES + dsw, Ah + ar);
        cp16(base + 1 * TILE_BYTES + dsw, Al + ar);
        cp16(base + 2 * TILE_BYTES + dsw, Bh + wr);
        cp16(base + 3 * TILE_BYTES + dsw, Bl + wr);
    }
    CP_COMMIT();
}

// Reordered: within each ks, issue the 16 MMAs of each split-term as an
// independent burst (hh, then hl, then lh) so writes to the same accumulator
// are 16 instructions apart instead of back-to-back (asm volatile pins order).
__device__ __forceinline__ void stage_compute(
    uint32_t sb, int buf, int wm, int wn, int lane, float acc[2][8][4])
{
    uint32_t base = sb + 1024 + buf * STAGE_BYTES;
    int lrow = lane & 15, lk = (lane >> 4) * 16;
    #pragma unroll
    for (int ks = 0; ks < 4; ks++) {
        int kb = ks * 32;
        uint32_t ah[2][4], al[2][4], bh[4][4], bl[4][4];
        #pragma unroll
        for (int mt = 0; mt < 2; mt++) {
            uint32_t ro = (uint32_t)((wm * 32 + mt * 16 + lrow) * 128 + kb + lk);
            ldsm4(ah[mt], base + 0 * TILE_BYTES + sw128(ro));
            ldsm4(al[mt], base + 1 * TILE_BYTES + sw128(ro));
        }
        #pragma unroll
        for (int p = 0; p < 4; p++) {
            uint32_t ro = (uint32_t)((wn * 64 + p * 16 + lrow) * 128 + kb + lk);
            ldsm4(bh[p], base + 2 * TILE_BYTES + sw128(ro));
            ldsm4(bl[p], base + 3 * TILE_BYTES + sw128(ro));
        }
        // term Ah*Bh
        #pragma unroll
        for (int mt = 0; mt < 2; mt++)
            #pragma unroll
            for (int p = 0; p < 4; p++) {
                mma16816(acc[mt][2*p],   ah[mt], bh[p][0], bh[p][2]);
                mma16816(acc[mt][2*p+1], ah[mt], bh[p][1], bh[p][3]);
            }
        // term Ah*Bl
        #pragma unroll
        for (int mt = 0; mt < 2; mt++)
            #pragma unroll
            for (int p = 0; p < 4; p++) {
                mma16816(acc[mt][2*p],   ah[mt], bl[p][0], bl[p][2]);
                mma16816(acc[mt][2*p+1], ah[mt], bl[p][1], bl[p][3]);
            }
        // term Al*Bh
        #pragma unroll
        for (int mt = 0; mt < 2; mt++)
            #pragma unroll
            for (int p = 0; p < 4; p++) {
                mma16816(acc[mt][2*p],   al[mt], bh[p][0], bh[p][2]);
                mma16816(acc[mt][2*p+1], al[mt], bh[p][1], bh[p][3]);
            }
    }
}

// ---------------- kernel 2: dense1 (HMMA split-bf16) + swiglu -> h hi/lo ----------------
__global__ __launch_bounds__(256, 1) void dense1_mma(const float* __restrict__ b1) {
    int e = blockIdx.z, rt = blockIdx.y, ct = blockIdx.x;
    int n = g_cnt[e];
    if (rt * TM >= n) return;

    extern __shared__ char smem[];
    int* s_tok = (int*)smem;
    int* s_val = (int*)(smem + 512);
    uint32_t sb = smem_u32(smem);
    int tid = threadIdx.x, lane = tid & 31, wid = tid >> 5;
    int wm = wid >> 1, wn = wid & 1;

    if (tid < TM) {
        int rg = rt * TM + tid;
        int cl = rg < n ? rg : n - 1;
        s_tok[tid] = g_entries[e][cl];
        s_val[tid] = rg < n;
    }
    __syncthreads();

    float acc[2][8][4];
    #pragma unroll
    for (int a = 0; a < 2; a++)
        #pragma unroll
        for (int b = 0; b < 8; b++)
            #pragma unroll
            for (int c = 0; c < 4; c++) acc[a][b][c] = 0.f;

    size_t brow0 = (size_t)e * TWO_F + (size_t)ct * TN;
    const int NS = D_DIM / KB;  // 16
    stage_load(sb, 0, 0, tid, s_tok, true, g_xh, g_xl, D_DIM, g_w1h, g_w1l, brow0, D_DIM);
    stage_load(sb, 1, KB, tid, s_tok, true, g_xh, g_xl, D_DIM, g_w1h, g_w1l, brow0, D_DIM);
    for (int s = 0; s < NS; s++) {
        if (s + 1 < NS) { CP_WAIT(1); } else { CP_WAIT(0); }
        __syncthreads();
        if (s + 2 < NS)
            stage_load(sb, (s + 2) % NSTAGE, (s + 2) * KB, tid, s_tok, true,
                       g_xh, g_xl, D_DIM, g_w1h, g_w1l, brow0, D_DIM);
        stage_compute(sb, s % NSTAGE, wm, wn, lane, acc);
    }

    // epilogue: swiglu on (gate, value) adjacent even/odd cols
    #pragma unroll
    for (int mt = 0; mt < 2; mt++) {
        #pragma unroll
        for (int nt = 0; nt < 8; nt++) {
            int c = ct * TN + wn * 64 + nt * 8 + (lane & 3) * 2;
            float bg = b1[e * TWO_F + c];
            float bv = b1[e * TWO_F + c + 1];
            #pragma unroll
            for (int hrow = 0; hrow < 2; hrow++) {
                int r = wm * 32 + mt * 16 + (lane >> 2) + hrow * 8;
                if (!s_val[r]) continue;
                int ts = s_tok[r];
                float gpre = acc[mt][nt][hrow * 2 + 0] + bg;
                float vpre = acc[mt][nt][hrow * 2 + 1] + bv;
                float gg = fminf(gpre, 9.0f);
                float vv = fminf(fmaxf(vpre, -9.0f), 9.0f);
                float h = gg * (1.0f / (1.0f + expf(-1.702f * gg))) * (vv + 1.0f);
                __nv_bfloat16 hh = __float2bfloat16(h);
                __nv_bfloat16 hl = __float2bfloat16(h - __bfloat162float(hh));
                size_t f = (size_t)ts * F_DIM + (c >> 1);
                g_hh[f] = hh;
                g_hl[f] = hl;
            }
        }
    }
}

// ---------------- kernel 3: dense2 (HMMA split-bf16) + bias + scale + atomic combine ----------------
__global__ __launch_bounds__(256, 1) void dense2_mma(const float* __restrict__ b2,
                                                     float* __restrict__ out) {
    int e = blockIdx.z, rt = blockIdx.y, ct = blockIdx.x;
    int n = g_cnt[e];
    if (rt * TM >= n) return;

    extern __shared__ char smem[];
    int* s_tok = (int*)smem;
    int* s_val = (int*)(smem + 512);
    uint32_t sb = smem_u32(smem);
    int tid = threadIdx.x, lane = tid & 31, wid = tid >> 5;
    int wm = wid >> 1, wn = wid & 1;

    if (tid < TM) {
        int rg = rt * TM + tid;
        int cl = rg < n ? rg : n - 1;
        s_tok[tid] = g_entries[e][cl];
        s_val[tid] = rg < n;
    }
    __syncthreads();

    float acc[2][8][4];
    #pragma unroll
    for (int a = 0; a < 2; a++)
        #pragma unroll
        for (int b = 0; b < 8; b++)
            #pragma unroll
            for (int c = 0; c < 4; c++) acc[a][b][c] = 0.f;

    size_t brow0 = (size_t)e * D_DIM + (size_t)ct * TN;
    const int NS = F_DIM / KB;  // 32
    stage_load(sb, 0, 0, tid, s_tok, false, g_hh, g_hl, F_DIM, g_w2h, g_w2l, brow0, F_DIM);
    stage_load(sb, 1, KB, tid, s_tok, false, g_hh, g_hl, F_DIM, g_w2h, g_w2l, brow0, F_DIM);
    for (int s = 0; s < NS; s++) {
        if (s + 1 < NS) { CP_WAIT(1); } else { CP_WAIT(0); }
        __syncthreads();
        if (s + 2 < NS)
            stage_load(sb, (s + 2) % NSTAGE, (s + 2) * KB, tid, s_tok, false,
                       g_hh, g_hl, F_DIM, g_w2h, g_w2l, brow0, F_DIM);
        stage_compute(sb, s % NSTAGE, wm, wn, lane, acc);
    }

    // epilogue: per output element exactly 2 expert contributions across the grid;
    // fp32 add is commutative, so atomicAdd onto zeroed out is bitwise deterministic.
    #pragma unroll
    for (int mt = 0; mt < 2; mt++) {
        #pragma unroll
        for (int hrow = 0; hrow < 2; hrow++) {
            int r = wm * 32 + mt * 16 + (lane >> 2) + hrow * 8;
            if (!s_val[r]) continue;
            int ts = s_tok[r];
            float wgt = g_wts[ts >> 1][ts & 1];
            float* yrow = out + (size_t)(ts >> 1) * D_DIM;
            #pragma unroll
            for (int nt = 0; nt < 8; nt++) {
                int c = ct * TN + wn * 64 + nt * 8 + (lane & 3) * 2;
                atomicAdd(yrow + c,     (acc[mt][nt][hrow * 2 + 0] + b2[e * D_DIM + c]) * wgt);
                atomicAdd(yrow + c + 1, (acc[mt][nt][hrow * 2 + 1] + b2[e * D_DIM + c + 1]) * wgt);
            }
        }
    }
}

// ---------------- launch ----------------
extern "C" void kernel_launch(void* const* d_in, const int* in_sizes, int n_in,
                              void* d_out, int out_size) {
    const float* x  = (const float*)d_in[0];
    const float* gw = (const float*)d_in[1];
    const float* w1 = (const float*)d_in[2];
    const float* b1 = (const float*)d_in[3];
    const float* w2 = (const float*)d_in[4];
    const float* b2 = (const float*)d_in[5];
    float* out = (float*)d_out;

    cudaFuncSetAttribute(dense1_mma, cudaFuncAttributeMaxDynamicSharedMemorySize, SMEM_BYTES);
    cudaFuncSetAttribute(dense2_mma, cudaFuncAttributeMaxDynamicSharedMemorySize, SMEM_BYTES);

    zero_all_kernel<<<(T_TOKENS * D_DIM / 4 + 255) / 256, 256>>>((float4*)out);
    cvt_all_kernel<<<(NW14 + NW24 + NX4 + 255) / 256, 256>>>(
        (const float4*)x, (const float4*)w1, (const float4*)w2);
    gate_kernel<<<T_TOKENS / 4, 128>>>(x, gw);
    dense1_mma<<<dim3(TWO_F / TN, T_TOKENS / TM, E_EXP), 256, SMEM_BYTES>>>(b1);
    dense2_mma<<<dim3(D_DIM / TN, T_TOKENS / TM, E_EXP), 256, SMEM_BYTES>>>(b2, out);
}

// round 9
// speedup vs baseline: 2.7349x; 1.0314x over previous
#include <cuda_runtime.h>
#include <cuda_bf16.h>
#include <math.h>
#include <stdint.h>

#define T_TOKENS 4096
#define D_DIM    1024
#define E_EXP    8
#define F_DIM    2048
#define TWO_F    4096
#define NPAIR    (T_TOKENS * 2)

#define TM 128
#define TN 128
#define KB 64                     // K elements per stage (64 bf16 = 128B rows, SW128)
#define TILE_BYTES 16384          // 128 rows * 128 B
#define STAGE_BYTES (4 * TILE_BYTES)
#define NSTAGE 3
#define SMEM_BYTES (1024 + NSTAGE * STAGE_BYTES)
#define NTHREADS 512

// ---------------- scratch (device globals; no allocs allowed) ----------------
__device__ int   g_cnt[E_EXP];
__device__ int   g_entries[E_EXP][T_TOKENS];
__device__ float g_wts[T_TOKENS][2];
__device__ __nv_bfloat16 g_xh[T_TOKENS * D_DIM];
__device__ __nv_bfloat16 g_xl[T_TOKENS * D_DIM];
__device__ __nv_bfloat16 g_w1h[(size_t)E_EXP * TWO_F * D_DIM];
__device__ __nv_bfloat16 g_w1l[(size_t)E_EXP * TWO_F * D_DIM];
__device__ __nv_bfloat16 g_w2h[(size_t)E_EXP * D_DIM * F_DIM];
__device__ __nv_bfloat16 g_w2l[(size_t)E_EXP * D_DIM * F_DIM];
__device__ __nv_bfloat16 g_hh[(size_t)NPAIR * F_DIM];
__device__ __nv_bfloat16 g_hl[(size_t)NPAIR * F_DIM];

// ---------------- helpers ----------------
__device__ __forceinline__ uint32_t smem_u32(const void* p) {
    uint32_t a;
    asm("{ .reg .u64 t; cvta.to.shared.u64 t, %1; cvt.u32.u64 %0, t; }" : "=r"(a) : "l"(p));
    return a;
}
__device__ __forceinline__ uint32_t sw128(uint32_t o) { return o ^ ((o >> 3) & 0x70); }

__device__ __forceinline__ void cp16(uint32_t dst, const void* src) {
    asm volatile("cp.async.cg.shared.global [%0], [%1], 16;" :: "r"(dst), "l"(src));
}
#define CP_COMMIT() asm volatile("cp.async.commit_group;" ::: "memory")
#define CP_WAIT(n)  asm volatile("cp.async.wait_group %0;" :: "n"(n) : "memory")

__device__ __forceinline__ void ldsm4(uint32_t* r, uint32_t addr) {
    asm volatile("ldmatrix.sync.aligned.m8n8.x4.shared.b16 {%0,%1,%2,%3}, [%4];"
        : "=r"(r[0]), "=r"(r[1]), "=r"(r[2]), "=r"(r[3]) : "r"(addr));
}
__device__ __forceinline__ void mma16816(float* d, const uint32_t* a, uint32_t b0, uint32_t b1) {
    asm volatile("mma.sync.aligned.m16n8k16.row.col.f32.bf16.bf16.f32 "
        "{%0,%1,%2,%3}, {%4,%5,%6,%7}, {%8,%9}, {%0,%1,%2,%3};"
        : "+f"(d[0]), "+f"(d[1]), "+f"(d[2]), "+f"(d[3])
        : "r"(a[0]), "r"(a[1]), "r"(a[2]), "r"(a[3]), "r"(b0), "r"(b1));
}

// ---------------- kernel 0: zero output + counters ----------------
__global__ void zero_all_kernel(float4* __restrict__ out) {
    int i = blockIdx.x * blockDim.x + threadIdx.x;
    if (i < T_TOKENS * D_DIM / 4) out[i] = make_float4(0.f, 0.f, 0.f, 0.f);
    if (blockIdx.x == 0 && threadIdx.x < E_EXP) g_cnt[threadIdx.x] = 0;
}

// ---------------- conversion: fp32 -> bf16 hi + lo (one launch) ----------------
__device__ __forceinline__ void cvt4(float4 f, uint2& H, uint2& L) {
    __nv_bfloat16 h0 = __float2bfloat16(f.x), h1 = __float2bfloat16(f.y);
    __nv_bfloat16 h2 = __float2bfloat16(f.z), h3 = __float2bfloat16(f.w);
    __nv_bfloat16 l0 = __float2bfloat16(f.x - __bfloat162float(h0));
    __nv_bfloat16 l1 = __float2bfloat16(f.y - __bfloat162float(h1));
    __nv_bfloat16 l2 = __float2bfloat16(f.z - __bfloat162float(h2));
    __nv_bfloat16 l3 = __float2bfloat16(f.w - __bfloat162float(h3));
    H.x = (uint32_t)__bfloat16_as_ushort(h0) | ((uint32_t)__bfloat16_as_ushort(h1) << 16);
    H.y = (uint32_t)__bfloat16_as_ushort(h2) | ((uint32_t)__bfloat16_as_ushort(h3) << 16);
    L.x = (uint32_t)__bfloat16_as_ushort(l0) | ((uint32_t)__bfloat16_as_ushort(l1) << 16);
    L.y = (uint32_t)__bfloat16_as_ushort(l2) | ((uint32_t)__bfloat16_as_ushort(l3) << 16);
}
#define NX4  (T_TOKENS * D_DIM / 4)
#define NW14 (E_EXP * TWO_F * D_DIM / 4)
#define NW24 (E_EXP * D_DIM * F_DIM / 4)
__global__ void cvt_all_kernel(const float4* __restrict__ x,
                               const float4* __restrict__ w1,
                               const float4* __restrict__ w2) {
    int i = blockIdx.x * blockDim.x + threadIdx.x;
    if (i < NW14) {
        uint2 H, L; cvt4(w1[i], H, L);
        ((uint2*)g_w1h)[i] = H; ((uint2*)g_w1l)[i] = L;
    } else if (i < NW14 + NW24) {
        int j = i - NW14;
        uint2 H, L; cvt4(w2[j], H, L);
        ((uint2*)g_w2h)[j] = H; ((uint2*)g_w2l)[j] = L;
    } else if (i < NW14 + NW24 + NX4) {
        int j = i - NW14 - NW24;
        uint2 H, L; cvt4(x[j], H, L);
        ((uint2*)g_xh)[j] = H; ((uint2*)g_xl)[j] = L;
    }
}

// ---------------- kernel 1: gate + top2 + routing ----------------
__global__ void gate_kernel(const float* __restrict__ x, const float* __restrict__ gw) {
    int warp = threadIdx.x >> 5;
    int lane = threadIdx.x & 31;
    int t = blockIdx.x * 4 + warp;
    float acc[8] = {0.f,0.f,0.f,0.f,0.f,0.f,0.f,0.f};
    const float* xr = x + (size_t)t * D_DIM;
    for (int d = lane; d < D_DIM; d += 32) {
        float xv = xr[d];
        const float* g = gw + d * 8;
        #pragma unroll
        for (int e = 0; e < 8; e++) acc[e] += xv * g[e];
    }
    #pragma unroll
    for (int off = 16; off > 0; off >>= 1)
        #pragma unroll
        for (int e = 0; e < 8; e++)
            acc[e] += __shfl_down_sync(0xffffffffu, acc[e], off);
    if (lane == 0) {
        int b0 = 0; float v0 = acc[0];
        #pragma unroll
        for (int e = 1; e < 8; e++) if (acc[e] > v0) { v0 = acc[e]; b0 = e; }
        int b1 = -1; float v1 = -3.4e38f;
        #pragma unroll
        for (int e = 0; e < 8; e++) if (e != b0 && acc[e] > v1) { v1 = acc[e]; b1 = e; }
        float w0 = 1.0f / (1.0f + expf(v1 - v0));
        g_wts[t][0] = w0;
        g_wts[t][1] = 1.0f - w0;
        int p0 = atomicAdd(&g_cnt[b0], 1);
        g_entries[b0][p0] = t * 2 + 0;
        int p1 = atomicAdd(&g_cnt[b1], 1);
        g_entries[b1][p1] = t * 2 + 1;
    }
}

// ---------------- shared GEMM machinery (512 threads, 16 warps, warp tile 32x32) ----------------
// smem: [0..512) s_tok, [512..1024) s_val, tiles at 1024: stage{0..2} x {AH,AL,BH,BL}
__device__ __forceinline__ void stage_load(
    uint32_t sb, int buf, int k0, int tid,
    const int* s_tok, bool a_is_pair,
    const __nv_bfloat16* Ah, const __nv_bfloat16* Al, int lda,
    const __nv_bfloat16* Bh, const __nv_bfloat16* Bl, size_t brow0, int ldb)
{
    uint32_t base = sb + 1024 + buf * STAGE_BYTES;
    #pragma unroll
    for (int ii = 0; ii < 2; ii++) {
        int i = tid + ii * NTHREADS;
        int r = i >> 3, v = i & 7;
        uint32_t dsw = sw128((uint32_t)(r * 128 + v * 16));
        int ts = s_tok[r];
        size_t ar = (size_t)(a_is_pair ? (ts >> 1) : ts) * lda + k0 + v * 8;
        size_t wr = (brow0 + r) * (size_t)ldb + k0 + v * 8;
        cp16(base + 0 * TILE_BYTES + dsw, Ah + ar);
        cp16(base + 1 * TILE_BYTES + dsw, Al + ar);
        cp16(base + 2 * TILE_BYTES + dsw, Bh + wr);
        cp16(base + 3 * TILE_BYTES + dsw, Bl + wr);
    }
    CP_COMMIT();
}

// warp tile 32(M) x 32(N): wm, wn in 0..3. Per k16 step: 8 ldsm4, 24 MMA
// (term-major bursts: same-accumulator writes are 8 MMAs apart).
__device__ __forceinline__ void stage_compute(
    uint32_t sb, int buf, int wm, int wn, int lane, float acc[2][4][4])
{
    uint32_t base = sb + 1024 + buf * STAGE_BYTES;
    int lrow = lane & 15, lk = (lane >> 4) * 16;
    #pragma unroll
    for (int ks = 0; ks < 4; ks++) {
        int kb = ks * 32;
        uint32_t ah[2][4], al[2][4], bh[2][4], bl[2][4];
        #pragma unroll
        for (int mt = 0; mt < 2; mt++) {
            uint32_t ro = (uint32_t)((wm * 32 + mt * 16 + lrow) * 128 + kb + lk);
            ldsm4(ah[mt], base + 0 * TILE_BYTES + sw128(ro));
            ldsm4(al[mt], base + 1 * TILE_BYTES + sw128(ro));
        }
        #pragma unroll
        for (int np = 0; np < 2; np++) {
            uint32_t ro = (uint32_t)((wn * 32 + np * 16 + lrow) * 128 + kb + lk);
            ldsm4(bh[np], base + 2 * TILE_BYTES + sw128(ro));
            ldsm4(bl[np], base + 3 * TILE_BYTES + sw128(ro));
        }
        // term Ah*Bh
        #pragma unroll
        for (int mt = 0; mt < 2; mt++)
            #pragma unroll
            for (int np = 0; np < 2; np++) {
                mma16816(acc[mt][2*np],   ah[mt], bh[np][0], bh[np][2]);
                mma16816(acc[mt][2*np+1], ah[mt], bh[np][1], bh[np][3]);
            }
        // term Ah*Bl
        #pragma unroll
        for (int mt = 0; mt < 2; mt++)
            #pragma unroll
            for (int np = 0; np < 2; np++) {
                mma16816(acc[mt][2*np],   ah[mt], bl[np][0], bl[np][2]);
                mma16816(acc[mt][2*np+1], ah[mt], bl[np][1], bl[np][3]);
            }
        // term Al*Bh
        #pragma unroll
        for (int mt = 0; mt < 2; mt++)
            #pragma unroll
            for (int np = 0; np < 2; np++) {
                mma16816(acc[mt][2*np],   al[mt], bh[np][0], bh[np][2]);
                mma16816(acc[mt][2*np+1], al[mt], bh[np][1], bh[np][3]);
            }
    }
}

// ---------------- kernel 2: dense1 (HMMA split-bf16) + swiglu -> h hi/lo ----------------
__global__ __launch_bounds__(NTHREADS, 1) void dense1_mma(const float* __restrict__ b1) {
    int e = blockIdx.z, rt = blockIdx.y, ct = blockIdx.x;
    int n = g_cnt[e];
    if (rt * TM >= n) return;

    extern __shared__ char smem[];
    int* s_tok = (int*)smem;
    int* s_val = (int*)(smem + 512);
    uint32_t sb = smem_u32(smem);
    int tid = threadIdx.x, lane = tid & 31, wid = tid >> 5;
    int wm = wid >> 2, wn = wid & 3;

    if (tid < TM) {
        int rg = rt * TM + tid;
        int cl = rg < n ? rg : n - 1;
        s_tok[tid] = g_entries[e][cl];
        s_val[tid] = rg < n;
    }
    __syncthreads();

    float acc[2][4][4];
    #pragma unroll
    for (int a = 0; a < 2; a++)
        #pragma unroll
        for (int b = 0; b < 4; b++)
            #pragma unroll
            for (int c = 0; c < 4; c++) acc[a][b][c] = 0.f;

    size_t brow0 = (size_t)e * TWO_F + (size_t)ct * TN;
    const int NS = D_DIM / KB;  // 16
    stage_load(sb, 0, 0, tid, s_tok, true, g_xh, g_xl, D_DIM, g_w1h, g_w1l, brow0, D_DIM);
    stage_load(sb, 1, KB, tid, s_tok, true, g_xh, g_xl, D_DIM, g_w1h, g_w1l, brow0, D_DIM);
    for (int s = 0; s < NS; s++) {
        if (s + 1 < NS) { CP_WAIT(1); } else { CP_WAIT(0); }
        __syncthreads();
        if (s + 2 < NS)
            stage_load(sb, (s + 2) % NSTAGE, (s + 2) * KB, tid, s_tok, true,
                       g_xh, g_xl, D_DIM, g_w1h, g_w1l, brow0, D_DIM);
        stage_compute(sb, s % NSTAGE, wm, wn, lane, acc);
    }

    // epilogue: swiglu on (gate, value) adjacent even/odd cols
    #pragma unroll
    for (int mt = 0; mt < 2; mt++) {
        #pragma unroll
        for (int nt = 0; nt < 4; nt++) {
            int c = ct * TN + wn * 32 + nt * 8 + (lane & 3) * 2;
            float bg = b1[e * TWO_F + c];
            float bv = b1[e * TWO_F + c + 1];
            #pragma unroll
            for (int hrow = 0; hrow < 2; hrow++) {
                int r = wm * 32 + mt * 16 + (lane >> 2) + hrow * 8;
                if (!s_val[r]) continue;
                int ts = s_tok[r];
                float gpre = acc[mt][nt][hrow * 2 + 0] + bg;
                float vpre = acc[mt][nt][hrow * 2 + 1] + bv;
                float gg = fminf(gpre, 9.0f);
                float vv = fminf(fmaxf(vpre, -9.0f), 9.0f);
                float h = gg * (1.0f / (1.0f + expf(-1.702f * gg))) * (vv + 1.0f);
                __nv_bfloat16 hh = __float2bfloat16(h);
                __nv_bfloat16 hl = __float2bfloat16(h - __bfloat162float(hh));
                size_t f = (size_t)ts * F_DIM + (c >> 1);
                g_hh[f] = hh;
                g_hl[f] = hl;
            }
        }
    }
}

// ---------------- kernel 3: dense2 (HMMA split-bf16) + bias + scale + atomic combine ----------------
__global__ __launch_bounds__(NTHREADS, 1) void dense2_mma(const float* __restrict__ b2,
                                                          float* __restrict__ out) {
    int e = blockIdx.z, rt = blockIdx.y, ct = blockIdx.x;
    int n = g_cnt[e];
    if (rt * TM >= n) return;

    extern __shared__ char smem[];
    int* s_tok = (int*)smem;
    int* s_val = (int*)(smem + 512);
    uint32_t sb = smem_u32(smem);
    int tid = threadIdx.x, lane = tid & 31, wid = tid >> 5;
    int wm = wid >> 2, wn = wid & 3;

    if (tid < TM) {
        int rg = rt * TM + tid;
        int cl = rg < n ? rg : n - 1;
        s_tok[tid] = g_entries[e][cl];
        s_val[tid] = rg < n;
    }
    __syncthreads();

    float acc[2][4][4];
    #pragma unroll
    for (int a = 0; a < 2; a++)
        #pragma unroll
        for (int b = 0; b < 4; b++)
            #pragma unroll
            for (int c = 0; c < 4; c++) acc[a][b][c] = 0.f;

    size_t brow0 = (size_t)e * D_DIM + (size_t)ct * TN;
    const int NS = F_DIM / KB;  // 32
    stage_load(sb, 0, 0, tid, s_tok, false, g_hh, g_hl, F_DIM, g_w2h, g_w2l, brow0, F_DIM);
    stage_load(sb, 1, KB, tid, s_tok, false, g_hh, g_hl, F_DIM, g_w2h, g_w2l, brow0, F_DIM);
    for (int s = 0; s < NS; s++) {
        if (s + 1 < NS) { CP_WAIT(1); } else { CP_WAIT(0); }
        __syncthreads();
        if (s + 2 < NS)
            stage_load(sb, (s + 2) % NSTAGE, (s + 2) * KB, tid, s_tok, false,
                       g_hh, g_hl, F_DIM, g_w2h, g_w2l, brow0, F_DIM);
        stage_compute(sb, s % NSTAGE, wm, wn, lane, acc);
    }

    // per output element exactly 2 expert contributions; fp32 atomicAdd onto
    // zeroed out is commutative -> deterministic.
    #pragma unroll
    for (int mt = 0; mt < 2; mt++) {
        #pragma unroll
        for (int hrow = 0; hrow < 2; hrow++) {
            int r = wm * 32 + mt * 16 + (lane >> 2) + hrow * 8;
            if (!s_val[r]) continue;
            int ts = s_tok[r];
            float wgt = g_wts[ts >> 1][ts & 1];
            float* yrow = out + (size_t)(ts >> 1) * D_DIM;
            #pragma unroll
            for (int nt = 0; nt < 4; nt++) {
                int c = ct * TN + wn * 32 + nt * 8 + (lane & 3) * 2;
                atomicAdd(yrow + c,     (acc[mt][nt][hrow * 2 + 0] + b2[e * D_DIM + c]) * wgt);
                atomicAdd(yrow + c + 1, (acc[mt][nt][hrow * 2 + 1] + b2[e * D_DIM + c + 1]) * wgt);
            }
        }
    }
}

// ---------------- launch ----------------
extern "C" void kernel_launch(void* const* d_in, const int* in_sizes, int n_in,
                              void* d_out, int out_size) {
    const float* x  = (const float*)d_in[0];
    const float* gw = (const float*)d_in[1];
    const float* w1 = (const float*)d_in[2];
    const float* b1 = (const float*)d_in[3];
    const float* w2 = (const float*)d_in[4];
    const float* b2 = (const float*)d_in[5];
    float* out = (float*)d_out;

    cudaFuncSetAttribute(dense1_mma, cudaFuncAttributeMaxDynamicSharedMemorySize, SMEM_BYTES);
    cudaFuncSetAttribute(dense2_mma, cudaFuncAttributeMaxDynamicSharedMemorySize, SMEM_BYTES);

    zero_all_kernel<<<(T_TOKENS * D_DIM / 4 + 255) / 256, 256>>>((float4*)out);
    cvt_all_kernel<<<(NW14 + NW24 + NX4 + 255) / 256, 256>>>(
        (const float4*)x, (const float4*)w1, (const float4*)w2);
    gate_kernel<<<T_TOKENS / 4, 128>>>(x, gw);
    dense1_mma<<<dim3(TWO_F / TN, T_TOKENS / TM, E_EXP), NTHREADS, SMEM_BYTES>>>(b1);
    dense2_mma<<<dim3(D_DIM / TN, T_TOKENS / TM, E_EXP), NTHREADS, SMEM_BYTES>>>(b2, out);
}